// round 1
// baseline (speedup 1.0000x reference)
#include <cuda_runtime.h>
#include <cuda_bf16.h>
#include <cstdint>

// GraphConv (GCN layer):
//   deg[d]   = # incoming edges at d (histogram over dst)
//   norm[i]  = rsqrt(max(deg[i],1))
//   agg[d]  += feat[s] * norm[s]   for each edge (s,d)
//   out      = (agg @ W) * norm + bias
//
// Shapes: feat [N,128] f32, W [128,128] f32, bias [128] f32,
//         src/dst [E] i32, out [N,128] f32.  N=100000, E=1600000.

#define D 128          // feature dim (in == out)
#define N_MAX 100000

// Scratch (allocation-free: __device__ globals)
__device__ float g_agg[(size_t)N_MAX * D];   // 51.2 MB
__device__ float g_deg[N_MAX];

// ---------------------------------------------------------------------------
// Pass 0: zero agg + deg
// ---------------------------------------------------------------------------
__global__ void zero_kernel(int n_nodes) {
    int i = blockIdx.x * blockDim.x + threadIdx.x;
    int nagg4 = n_nodes * (D / 4);
    if (i < nagg4) {
        reinterpret_cast<float4*>(g_agg)[i] = make_float4(0.f, 0.f, 0.f, 0.f);
    }
    if (i < n_nodes) g_deg[i] = 0.f;
}

// ---------------------------------------------------------------------------
// Pass 1: in-degree histogram over dst
// ---------------------------------------------------------------------------
__global__ void hist_kernel(const int* __restrict__ dst, int n_edges) {
    int e = blockIdx.x * blockDim.x + threadIdx.x;
    if (e < n_edges) {
        atomicAdd(&g_deg[dst[e]], 1.0f);
    }
}

// ---------------------------------------------------------------------------
// Pass 2: edge scatter. One warp per edge; lane l handles cols [4l, 4l+4).
// feat row gather is 512B coalesced; scatter uses red.global.add.v4.f32
// (sm_90+) = 1 reduction instr per 16B instead of 4 scalar atomics.
// ---------------------------------------------------------------------------
__global__ void scatter_kernel(const float4* __restrict__ feat4,
                               const int* __restrict__ src,
                               const int* __restrict__ dst,
                               int n_edges) {
    int warp = (blockIdx.x * blockDim.x + threadIdx.x) >> 5;
    int lane = threadIdx.x & 31;
    if (warp >= n_edges) return;

    int s = __ldg(src + warp);
    int d = __ldg(dst + warp);
    float ns = rsqrtf(fmaxf(__ldg(&g_deg[s]), 1.0f));   // norm[src]

    float4 v = __ldg(feat4 + (size_t)s * (D / 4) + lane);
    v.x *= ns; v.y *= ns; v.z *= ns; v.w *= ns;

    float* p = g_agg + (size_t)d * D + lane * 4;
    asm volatile("red.global.add.v4.f32 [%0], {%1, %2, %3, %4};"
                 :: "l"(p), "f"(v.x), "f"(v.y), "f"(v.z), "f"(v.w)
                 : "memory");
}

// ---------------------------------------------------------------------------
// Pass 3: out = (agg @ W) * norm + bias
// Block: 256 threads = (16 tx, 16 ty). Tile: 64 rows x 128 cols (all cols).
// Each thread: 4 rows x 8 cols (cols = {tx*4..tx*4+3, 64+tx*4..+3}) so the
// float4 LDS of W is phase-conflict-free without padding.
// smem: W[128][128] (64KB) + A[64][128] (32KB) -> dynamic smem 96KB.
// ---------------------------------------------------------------------------
#define TM 64
__global__ __launch_bounds__(256, 2)
void matmul_kernel(const float* __restrict__ W,
                   const float* __restrict__ bias,
                   float* __restrict__ out, int n_nodes) {
    extern __shared__ float sm[];
    float* sW = sm;              // 128*128
    float* sA = sm + D * D;      // 64*128

    int t  = threadIdx.x;
    int tx = t & 15;
    int ty = t >> 4;
    int bm = blockIdx.x * TM;
    int rows = min(TM, n_nodes - bm);

    // Load W (16384 floats = 4096 float4, 16 per thread), coalesced.
    {
        float4*       sW4 = reinterpret_cast<float4*>(sW);
        const float4* W4  = reinterpret_cast<const float4*>(W);
#pragma unroll
        for (int i = 0; i < 16; i++) sW4[t + i * 256] = __ldg(W4 + t + i * 256);
    }
    // Load A tile (rows x 128 = up to 2048 float4, 8 per thread).
    {
        float4*       sA4 = reinterpret_cast<float4*>(sA);
        const float4* A4  = reinterpret_cast<const float4*>(g_agg);
#pragma unroll
        for (int i = 0; i < 8; i++) {
            int idx = t + i * 256;        // 0..2047
            int r   = idx >> 5;           // row within tile
            if (r < rows) sA4[idx] = A4[(size_t)(bm + r) * (D / 4) + (idx & 31)];
        }
    }
    __syncthreads();

    float acc[4][8];
#pragma unroll
    for (int i = 0; i < 4; i++)
#pragma unroll
        for (int j = 0; j < 8; j++) acc[i][j] = 0.f;

#pragma unroll 4
    for (int k = 0; k < D; k++) {
        float a0 = sA[(ty * 4 + 0) * D + k];
        float a1 = sA[(ty * 4 + 1) * D + k];
        float a2 = sA[(ty * 4 + 2) * D + k];
        float a3 = sA[(ty * 4 + 3) * D + k];
        float4 b0 = *reinterpret_cast<float4*>(&sW[k * D + tx * 4]);
        float4 b1 = *reinterpret_cast<float4*>(&sW[k * D + 64 + tx * 4]);
        float b[8] = {b0.x, b0.y, b0.z, b0.w, b1.x, b1.y, b1.z, b1.w};
        float a[4] = {a0, a1, a2, a3};
#pragma unroll
        for (int i = 0; i < 4; i++)
#pragma unroll
            for (int j = 0; j < 8; j++) acc[i][j] = fmaf(a[i], b[j], acc[i][j]);
    }

    // Epilogue: *norm + bias, vectorized stores.
    float4 bia0 = __ldg(reinterpret_cast<const float4*>(bias) + tx);
    float4 bia1 = __ldg(reinterpret_cast<const float4*>(bias) + 16 + tx);
#pragma unroll
    for (int i = 0; i < 4; i++) {
        int r = bm + ty * 4 + i;
        if (r < n_nodes) {
            float nr = rsqrtf(fmaxf(g_deg[r], 1.0f));
            float4 o0, o1;
            o0.x = fmaf(acc[i][0], nr, bia0.x);
            o0.y = fmaf(acc[i][1], nr, bia0.y);
            o0.z = fmaf(acc[i][2], nr, bia0.z);
            o0.w = fmaf(acc[i][3], nr, bia0.w);
            o1.x = fmaf(acc[i][4], nr, bia1.x);
            o1.y = fmaf(acc[i][5], nr, bia1.y);
            o1.z = fmaf(acc[i][6], nr, bia1.z);
            o1.w = fmaf(acc[i][7], nr, bia1.w);
            float4* out4 = reinterpret_cast<float4*>(out) + (size_t)r * (D / 4);
            out4[tx]      = o0;
            out4[16 + tx] = o1;
        }
    }
}

// ---------------------------------------------------------------------------
extern "C" void kernel_launch(void* const* d_in, const int* in_sizes, int n_in,
                              void* d_out, int out_size) {
    const float4* feat4 = (const float4*)d_in[0];
    const float*  W     = (const float*)d_in[1];
    const float*  bias  = (const float*)d_in[2];
    const int*    src   = (const int*)d_in[3];
    const int*    dst   = (const int*)d_in[4];
    float*        out   = (float*)d_out;

    int n_nodes = in_sizes[0] / D;
    int n_edges = in_sizes[3];

    // Pass 0: zero scratch
    int nagg4 = n_nodes * (D / 4);
    zero_kernel<<<(nagg4 + 255) / 256, 256>>>(n_nodes);

    // Pass 1: degree histogram
    hist_kernel<<<(n_edges + 255) / 256, 256>>>(dst, n_edges);

    // Pass 2: scatter (one warp per edge)
    int sblocks = (n_edges + 7) / 8;   // 8 warps per 256-thread block
    scatter_kernel<<<sblocks, 256>>>(feat4, src, dst, n_edges);

    // Pass 3: matmul + norm + bias
    size_t smem = (size_t)(D * D + TM * D) * sizeof(float);   // 96 KB
    cudaFuncSetAttribute(matmul_kernel,
                         cudaFuncAttributeMaxDynamicSharedMemorySize, (int)smem);
    matmul_kernel<<<(n_nodes + TM - 1) / TM, 256, smem>>>(W, bias, out, n_nodes);
}